// round 16
// baseline (speedup 1.0000x reference)
#include <cuda_runtime.h>
#include <cuda_fp16.h>
#include <cstdint>

// ---------------- problem constants ----------------
#define LNUM 8
#define BNUM 1024
#define DNUM 1024
#define FNUM 8192
#define KC   32              // fp32 K elements per chunk

#define STW   4096           // stage words: [Ah 2048 | Bh 2048] (16 KB)
#define STB   (STW * 4)
#define DEC_BLOCKS 512

// decoder warp-spec config
#define DNTHR  512           // 8 consumer warps + 8 producer warps
#define NSTAGE 4

static const long long FEATS_OFF = (long long)LNUM * BNUM * DNUM;               // 8388608
static const long long LOSS_OFF  = FEATS_OFF + (long long)LNUM * BNUM * FNUM;   // 75497472

// ---------------- global accumulators ----------------
__device__ double g_sp_sum;
__device__ double g_sq_sum;
__device__ unsigned long long g_cnt[LNUM];
__device__ int    g_done;

__global__ void init_acc_kernel() {
    g_sp_sum = 0.0;
    g_sq_sum = 0.0;
    for (int i = 0; i < LNUM; ++i) g_cnt[i] = 0ull;
    g_done = 0;
}

__global__ void spacer_kernel() {}   // keeps decoder at the ncu-profiled launch slot

// ---------------- small helpers ----------------
__device__ __forceinline__ uint32_t smem_u32(const void* p) {
    uint32_t a;
    asm("{ .reg .u64 t; cvta.to.shared.u64 t, %1; cvt.u32.u64 %0, t; }" : "=r"(a) : "l"(p));
    return a;
}
__device__ __forceinline__ void lds128(uint32_t (&r)[4], uint32_t addr) {
    asm volatile("ld.shared.v4.b32 {%0,%1,%2,%3}, [%4];"
        : "=r"(r[0]), "=r"(r[1]), "=r"(r[2]), "=r"(r[3]) : "r"(addr));
}
__device__ __forceinline__ void mma16816(float (&c)[4], const uint32_t (&a)[4],
                                         uint32_t b0, uint32_t b1) {
    asm volatile("mma.sync.aligned.m16n8k16.row.col.f32.f16.f16.f32 "
        "{%0,%1,%2,%3}, {%4,%5,%6,%7}, {%8,%9}, {%0,%1,%2,%3};"
        : "+f"(c[0]), "+f"(c[1]), "+f"(c[2]), "+f"(c[3])
        : "r"(a[0]), "r"(a[1]), "r"(a[2]), "r"(a[3]), "r"(b0), "r"(b1));
}
__device__ __forceinline__ uint32_t pack16(float x, float y) {
    uint32_t h;
    asm("cvt.rn.f16x2.f32 %0, %1, %2;" : "=r"(h) : "f"(y), "f"(x));
    return h;
}
#define MEMBAR_CTA() asm volatile("membar.cta;" ::: "memory")
__device__ __forceinline__ void nbar_sync(int id) {
    asm volatile("bar.sync %0, %1;" :: "r"(id), "n"(DNTHR) : "memory");
}
__device__ __forceinline__ void nbar_arrive(int id) {
    asm volatile("bar.arrive %0, %1;" :: "r"(id), "n"(DNTHR) : "memory");
}

// producer slot bases: aslot[i] = aslot0 + 256*i, bslot[i] = bslot0 + 256*i
__device__ __forceinline__ void prod_bases(int tid, int& aslot0, int& bslot0, int& goff0_pc) {
    const int rbase = tid >> 4;       // 0..15
    const int pc    = tid & 15;
    const int kt_p  = pc >> 3, kk = pc & 7, tt = kk & 3, kh = kk >> 2;
    const int g = rbase & 7, rh = rbase >> 3;
    aslot0 = (kt_p << 7) + ((g * 4 + tt) << 2) + (rh + 2 * kh);
    bslot0 = (rh << 7) + ((g * 4 + tt) << 2) + kt_p * 2 + kh;
    goff0_pc = 2 * pc;
}

// packed prefetch (encoder producer): LDG float2 -> fp16x2 hi regs
template <int KDIM>
__device__ __forceinline__ void load_pack(const float* Ap, const float* Bp,
                                          uint32_t (&ar)[8], uint32_t (&br)[8]) {
#pragma unroll
    for (int i = 0; i < 8; ++i) {
        float2 v = *(const float2*)(Ap + i * 16 * KDIM);
        ar[i] = pack16(v.x, v.y);
    }
#pragma unroll
    for (int i = 0; i < 8; ++i) {
        float2 v = *(const float2*)(Bp + i * 16 * KDIM);
        br[i] = pack16(v.x, v.y);
    }
}

__device__ __forceinline__ void sts_chunk(uint32_t* st, int aslot0, int bslot0,
                                          const uint32_t (&ar)[8], const uint32_t (&br)[8]) {
#pragma unroll
    for (int i = 0; i < 8; ++i) {
        st[aslot0 + 256 * i]        = ar[i];
        st[2048 + bslot0 + 256 * i] = br[i];
    }
}

// ---------------- consumer: one K=32 chunk, 1-term (hi x hi) ----------------
__device__ __forceinline__ void consume_chunk1(uint32_t base, int lane, int wm, int wn,
                                               float (&acc)[4][4][4]) {
    uint32_t bh[4][4];
#pragma unroll
    for (int n = 0; n < 4; ++n) {
        const uint32_t boff = ((wn * 4 + n) << 9) + lane * 16;
        lds128(bh[n], base + 2048 * 4 + boff);
    }
#pragma unroll
    for (int kt = 0; kt < 2; ++kt) {
        uint32_t ah[4][4];
#pragma unroll
        for (int m = 0; m < 4; ++m) {
            const uint32_t aoff = ((((wm * 4 + m) * 2) + kt) << 9) + lane * 16;
            lds128(ah[m], base + aoff);
        }
#pragma unroll
        for (int m = 0; m < 4; ++m)
#pragma unroll
            for (int n = 0; n < 4; ++n)
                mma16816(acc[m][n], ah[m], bh[n][kt * 2], bh[n][kt * 2 + 1]);
    }
}

// ---------------- encoder (R15-proven: 128x128, 256 thr, occ 2, 1-term, prefetch) ----
__global__ __launch_bounds__(256, 2) void encoder_mma(const float* __restrict__ resid,
                                                      const float* __restrict__ enc_w,
                                                      const float* __restrict__ enc_b,
                                                      float* __restrict__ out) {
    extern __shared__ uint32_t smraw[];
    __shared__ float sbias[128];
    __shared__ float s_sp[8];
    __shared__ int   s_cnt[8];

    const int tid = threadIdx.x;
    const int l   = blockIdx.z;
    const int m0  = blockIdx.y * 128;
    const int n0  = blockIdx.x * 128;
    const uint32_t smb = smem_u32(smraw);

    if (tid < 128) sbias[tid] = enc_b[(long long)l * FNUM + n0 + tid];

    int aslot0, bslot0, gpc;
    prod_bases(tid, aslot0, bslot0, gpc);
    const int rbase = tid >> 4;
    const float* Ap = resid + ((long long)l * BNUM + m0 + rbase) * DNUM + gpc;
    const float* Bp = enc_w + ((long long)l * FNUM + n0 + rbase) * DNUM + gpc;

    float acc[4][4][4];
#pragma unroll
    for (int m = 0; m < 4; ++m)
#pragma unroll
        for (int n = 0; n < 4; ++n)
#pragma unroll
            for (int q = 0; q < 4; ++q) acc[m][n][q] = 0.0f;

    const int lane = tid & 31, wid = tid >> 5;
    const int wm = wid >> 2, wn = wid & 3;

    uint32_t ar[8], br[8];
    load_pack<DNUM>(Ap, Bp, ar, br);
    sts_chunk(smraw, aslot0, bslot0, ar, br);

    const int NC = DNUM / KC;   // 32
    for (int c = 0; c < NC; ++c) {
        __syncthreads();
        if (c + 1 < NC) {
            Ap += KC;
            Bp += KC;
            load_pack<DNUM>(Ap, Bp, ar, br);
        }
        consume_chunk1(smb + (c & 1) * STB, lane, wm, wn, acc);
        if (c + 1 < NC)
            sts_chunk(smraw + ((c + 1) & 1) * STW, aslot0, bslot0, ar, br);
    }

    const int g = lane >> 2, tt = lane & 3;

    float sp = 0.0f;
    int   cnt = 0;
#pragma unroll
    for (int m = 0; m < 4; ++m) {
        const int r0 = m0 + wm * 64 + m * 16 + g;
#pragma unroll
        for (int n = 0; n < 4; ++n) {
            const int cl  = wn * 32 + n * 8 + tt * 2;
            const float b0 = sbias[cl], b1 = sbias[cl + 1];
            float x0 = fmaxf(acc[m][n][0] + b0, 0.0f);
            float x1 = fmaxf(acc[m][n][1] + b1, 0.0f);
            float x2 = fmaxf(acc[m][n][2] + b0, 0.0f);
            float x3 = fmaxf(acc[m][n][3] + b1, 0.0f);
            sp  += (x0 + x1) + (x2 + x3);
            cnt += (x0 > 0.0f) + (x1 > 0.0f) + (x2 > 0.0f) + (x3 > 0.0f);
            float* p0 = out + FEATS_OFF + ((long long)l * BNUM + r0) * FNUM + n0 + cl;
            float* p1 = out + FEATS_OFF + ((long long)l * BNUM + r0 + 8) * FNUM + n0 + cl;
            *(float2*)p0 = make_float2(x0, x1);
            *(float2*)p1 = make_float2(x2, x3);
        }
    }
#pragma unroll
    for (int o = 16; o > 0; o >>= 1) {
        sp  += __shfl_down_sync(0xffffffffu, sp, o);
        cnt += __shfl_down_sync(0xffffffffu, cnt, o);
    }
    if (lane == 0) { s_sp[wid] = sp; s_cnt[wid] = cnt; }
    __syncthreads();
    if (tid == 0) {
        float tsp = 0.0f; int tc = 0;
        for (int w = 0; w < 8; ++w) { tsp += s_sp[w]; tc += s_cnt[w]; }
        atomicAdd(&g_sp_sum, (double)tsp);
        atomicAdd(&g_cnt[l], (unsigned long long)tc);
    }
}

// ---------------- decoder: warp-specialized (8 cons + 8 prod warps, 4-stage ring) -----
// FULL barriers: 1 + s (s=0..3). EMPTY barriers: 5 + s.
__global__ __launch_bounds__(DNTHR) void decoder_mma(const float* __restrict__ feats,
                                                     const float* __restrict__ dec_w,
                                                     const float* __restrict__ tgt,
                                                     float* __restrict__ out) {
    extern __shared__ uint32_t smraw[];
    __shared__ float s_sq[8];

    const int tid = threadIdx.x;
    const int bid = blockIdx.x;
    const int t   = 7 - (bid >> 6);      // t descending: 3-segment CTAs first
    const int rem = bid & 63;
    const int m0  = (rem >> 3) * 128;
    const int n0  = (rem & 7) * 128;
    const uint32_t smb = smem_u32(smraw);

    const int s_lo = (t >= 2) ? (t - 2) : 0;
    const int nseg = t - s_lo + 1;
    const int NC   = nseg * (FNUM / KC);   // nseg * 256

    const int lane = tid & 31, wid = tid >> 5;

    float acc[4][4][4];

    if (tid < 256) {
        // ---------------- consumer warps ----------------
#pragma unroll
        for (int m = 0; m < 4; ++m)
#pragma unroll
            for (int n = 0; n < 4; ++n)
#pragma unroll
                for (int q = 0; q < 4; ++q) acc[m][n][q] = 0.0f;
        const int wm = wid >> 2, wn = wid & 3;
        for (int c = 0; c < NC; ++c) {
            const int s = c & 3;
            nbar_sync(1 + s);
            consume_chunk1(smb + s * STB, lane, wm, wn, acc);
            nbar_arrive(5 + s);
        }
    } else {
        // ---------------- producer warps ----------------
        const int pt = tid - 256;            // 0..255
        int aslot0, bslot0, gpc;
        prod_bases(pt, aslot0, bslot0, gpc);
        const int rbase = pt >> 4;

        // pointer state for the chunk to LOAD next
        const float* Ap = feats + ((long long)s_lo * BNUM + m0 + rbase) * FNUM + gpc;
        const int pb0 = ((s_lo <= 5) ? (3 * s_lo) : (2 * s_lo + 6)) + (t - s_lo);
        const float* Bp = dec_w + ((long long)pb0 * DNUM + n0 + rbase) * FNUM + gpc;

        // double-buffered raw registers: LDG(c+1) overlaps cvt/STS(c)
        float2 a0[8], b0[8], a1[8], b1[8];
#pragma unroll
        for (int i = 0; i < 8; ++i) {
            a0[i] = *(const float2*)(Ap + i * 16 * FNUM);
            b0[i] = *(const float2*)(Bp + i * 16 * FNUM);
        }

        for (int c = 0; c < NC; ++c) {
            const int s = c & 3;
            if (c >= NSTAGE) nbar_sync(5 + s);
            // issue next chunk's LDGs first (into the other set)
            if (c + 1 < NC) {
                const int cn = c + 1;
                if ((cn & 255) == 0) {
                    const int sg = s_lo + (cn >> 8);
                    const int pb = ((sg <= 5) ? (3 * sg) : (2 * sg + 6)) + (t - sg);
                    Ap = feats + ((long long)sg * BNUM + m0 + rbase) * FNUM + gpc;
                    Bp = dec_w + ((long long)pb * DNUM + n0 + rbase) * FNUM + gpc;
                } else {
                    Ap += KC;
                    Bp += KC;
                }
                if ((c & 1) == 0) {
#pragma unroll
                    for (int i = 0; i < 8; ++i) {
                        a1[i] = *(const float2*)(Ap + i * 16 * FNUM);
                        b1[i] = *(const float2*)(Bp + i * 16 * FNUM);
                    }
                } else {
#pragma unroll
                    for (int i = 0; i < 8; ++i) {
                        a0[i] = *(const float2*)(Ap + i * 16 * FNUM);
                        b0[i] = *(const float2*)(Bp + i * 16 * FNUM);
                    }
                }
            }
            // cvt + STS the current set into stage s
            uint32_t* st = smraw + s * STW;
            if ((c & 1) == 0) {
#pragma unroll
                for (int i = 0; i < 8; ++i) {
                    st[aslot0 + 256 * i]        = pack16(a0[i].x, a0[i].y);
                    st[2048 + bslot0 + 256 * i] = pack16(b0[i].x, b0[i].y);
                }
            } else {
#pragma unroll
                for (int i = 0; i < 8; ++i) {
                    st[aslot0 + 256 * i]        = pack16(a1[i].x, a1[i].y);
                    st[2048 + bslot0 + 256 * i] = pack16(b1[i].x, b1[i].y);
                }
            }
            MEMBAR_CTA();
            nbar_arrive(1 + s);
        }
    }

    // ---------------- epilogue (consumers only) ----------------
    if (tid < 256) {
        const int wm = wid >> 2, wn = wid & 3;
        const int g = lane >> 2, tt = lane & 3;
        float sq = 0.0f;
#pragma unroll
        for (int m = 0; m < 4; ++m) {
            const int r0 = m0 + wm * 64 + m * 16 + g;
#pragma unroll
            for (int n = 0; n < 4; ++n) {
                const int col = n0 + wn * 32 + n * 8 + tt * 2;
                const long long row0 = (long long)t * BNUM + r0;
                const long long row1 = row0 + 8;
                float2 t0 = *(const float2*)(tgt + row0 * DNUM + col);
                float2 t1 = *(const float2*)(tgt + row1 * DNUM + col);
                const float v0 = acc[m][n][0], v1 = acc[m][n][1];
                const float v2 = acc[m][n][2], v3 = acc[m][n][3];
                float d0 = v0 - t0.x, d1 = v1 - t0.y, d2 = v2 - t1.x, d3 = v3 - t1.y;
                sq = fmaf(d0, d0, sq); sq = fmaf(d1, d1, sq);
                sq = fmaf(d2, d2, sq); sq = fmaf(d3, d3, sq);
                *(float2*)(out + row0 * DNUM + col) = make_float2(v0, v1);
                *(float2*)(out + row1 * DNUM + col) = make_float2(v2, v3);
            }
        }
#pragma unroll
        for (int o = 16; o > 0; o >>= 1) sq += __shfl_down_sync(0xffffffffu, sq, o);
        if (lane == 0) s_sq[wid] = sq;
    }
    __syncthreads();
    if (tid == 0) {
        float tsq = 0.0f;
        for (int w = 0; w < 8; ++w) tsq += s_sq[w];
        atomicAdd(&g_sq_sum, (double)tsq);

        __threadfence();
        const int old = atomicAdd(&g_done, 1);
        if (old == DEC_BLOCKS - 1) {
            g_done = 0;
            double rl = g_sq_sum / ((double)LNUM * (double)BNUM * (double)DNUM);
            double sl = 1e-4 * (g_sp_sum / ((double)LNUM * (double)BNUM * (double)FNUM));
            out[LOSS_OFF + 0] = (float)(rl + sl);
            out[LOSS_OFF + 1] = (float)rl;
            out[LOSS_OFF + 2] = (float)sl;
            for (int i = 0; i < LNUM; ++i)
                out[LOSS_OFF + 3 + i] = (float)((double)g_cnt[i] / (double)BNUM);
        }
    }
}

// ---------------- entry point ----------------
#define SMEM_ENC (2 * STW * 4)        // 32 KB
#define SMEM_DEC (NSTAGE * STW * 4)   // 64 KB

extern "C" void kernel_launch(void* const* d_in, const int* in_sizes, int n_in,
                              void* d_out, int out_size) {
    (void)in_sizes; (void)n_in; (void)out_size;
    const float* resid   = (const float*)d_in[0];
    const float* targets = (const float*)d_in[1];
    const float* enc_w   = (const float*)d_in[2];
    const float* enc_b   = (const float*)d_in[3];
    const float* dec_w   = (const float*)d_in[4];
    float* out = (float*)d_out;

    static bool attr_done = false;
    if (!attr_done) {
        cudaFuncSetAttribute(encoder_mma, cudaFuncAttributeMaxDynamicSharedMemorySize, SMEM_ENC);
        cudaFuncSetAttribute(decoder_mma, cudaFuncAttributeMaxDynamicSharedMemorySize, SMEM_DEC);
        attr_done = true;
    }

    init_acc_kernel<<<1, 1>>>();

    dim3 genc(FNUM / 128, BNUM / 128, LNUM);  // (64, 8, 8)
    encoder_mma<<<genc, 256, SMEM_ENC>>>(resid, enc_w, enc_b, out);

    spacer_kernel<<<1, 32>>>();   // keeps decoder at ncu's profiled launch slot

    decoder_mma<<<DEC_BLOCKS, DNTHR, SMEM_DEC>>>(out + FEATS_OFF, dec_w, targets, out);
}

// round 17
// speedup vs baseline: 1.2848x; 1.2848x over previous
#include <cuda_runtime.h>
#include <cuda_fp16.h>
#include <cstdint>

// ---------------- problem constants ----------------
#define LNUM 8
#define BNUM 1024
#define DNUM 1024
#define FNUM 8192

// encoder: KC=32, stage [Ah 2048 | Bh 2048] (16 KB)
#define KC_E  32
#define STW_E 4096
// decoder: KC=64, two K32 sub-stages of [Ah 2048 | Bh 2048]
#define KC_D  64
#define SUBW_D 4096
#define STW_D (2 * SUBW_D)    // 32 KB

#define DEC_BLOCKS 512

static const long long FEATS_OFF = (long long)LNUM * BNUM * DNUM;               // 8388608
static const long long LOSS_OFF  = FEATS_OFF + (long long)LNUM * BNUM * FNUM;   // 75497472

// ---------------- global accumulators ----------------
__device__ double g_sp_sum;
__device__ double g_sq_sum;
__device__ unsigned long long g_cnt[LNUM];
__device__ int    g_done;

__global__ void init_acc_kernel() {
    g_sp_sum = 0.0;
    g_sq_sum = 0.0;
    for (int i = 0; i < LNUM; ++i) g_cnt[i] = 0ull;
    g_done = 0;
}

__global__ void spacer_kernel() {}   // keeps decoder at the ncu-profiled launch slot

// ---------------- small helpers ----------------
__device__ __forceinline__ uint32_t smem_u32(const void* p) {
    uint32_t a;
    asm("{ .reg .u64 t; cvta.to.shared.u64 t, %1; cvt.u32.u64 %0, t; }" : "=r"(a) : "l"(p));
    return a;
}
__device__ __forceinline__ void lds128(uint32_t (&r)[4], uint32_t addr) {
    asm volatile("ld.shared.v4.b32 {%0,%1,%2,%3}, [%4];"
        : "=r"(r[0]), "=r"(r[1]), "=r"(r[2]), "=r"(r[3]) : "r"(addr));
}
__device__ __forceinline__ void mma16816(float (&c)[4], const uint32_t (&a)[4],
                                         uint32_t b0, uint32_t b1) {
    asm volatile("mma.sync.aligned.m16n8k16.row.col.f32.f16.f16.f32 "
        "{%0,%1,%2,%3}, {%4,%5,%6,%7}, {%8,%9}, {%0,%1,%2,%3};"
        : "+f"(c[0]), "+f"(c[1]), "+f"(c[2]), "+f"(c[3])
        : "r"(a[0]), "r"(a[1]), "r"(a[2]), "r"(a[3]), "r"(b0), "r"(b1));
}
__device__ __forceinline__ uint32_t pack16(float x, float y) {
    uint32_t h;
    asm("cvt.rn.f16x2.f32 %0, %1, %2;" : "=r"(h) : "f"(y), "f"(x));
    return h;
}

// producer slot bases: aslot[i] = aslot0 + 256*i, bslot[i] = bslot0 + 256*i
__device__ __forceinline__ void prod_bases(int tid, int& aslot0, int& bslot0, int& goff0_pc) {
    const int rbase = tid >> 4;       // 0..15
    const int pc    = tid & 15;
    const int kt_p  = pc >> 3, kk = pc & 7, tt = kk & 3, kh = kk >> 2;
    const int g = rbase & 7, rh = rbase >> 3;
    aslot0 = (kt_p << 7) + ((g * 4 + tt) << 2) + (rh + 2 * kh);
    bslot0 = (rh << 7) + ((g * 4 + tt) << 2) + kt_p * 2 + kh;
    goff0_pc = 2 * pc;
}

// ---------------- consumer: one K=32 chunk, 1-term (hi x hi) ----------------
// stage: [Ah 2048w | Bh 2048w]
__device__ __forceinline__ void consume_chunk1(uint32_t base, int lane, int wm, int wn,
                                               float (&acc)[4][4][4]) {
    uint32_t bh[4][4];
#pragma unroll
    for (int n = 0; n < 4; ++n) {
        const uint32_t boff = ((wn * 4 + n) << 9) + lane * 16;
        lds128(bh[n], base + 2048 * 4 + boff);
    }
#pragma unroll
    for (int kt = 0; kt < 2; ++kt) {
        uint32_t ah[4][4];
#pragma unroll
        for (int m = 0; m < 4; ++m) {
            const uint32_t aoff = ((((wm * 4 + m) * 2) + kt) << 9) + lane * 16;
            lds128(ah[m], base + aoff);
        }
#pragma unroll
        for (int m = 0; m < 4; ++m)
#pragma unroll
            for (int n = 0; n < 4; ++n)
                mma16816(acc[m][n], ah[m], bh[n][kt * 2], bh[n][kt * 2 + 1]);
    }
}

// ---------------- encoder producer (R15): packed register prefetch ----------------
template <int KDIM>
__device__ __forceinline__ void load_pack(const float* Ap, const float* Bp,
                                          uint32_t (&ar)[8], uint32_t (&br)[8]) {
#pragma unroll
    for (int i = 0; i < 8; ++i) {
        float2 v = *(const float2*)(Ap + i * 16 * KDIM);
        ar[i] = pack16(v.x, v.y);
    }
#pragma unroll
    for (int i = 0; i < 8; ++i) {
        float2 v = *(const float2*)(Bp + i * 16 * KDIM);
        br[i] = pack16(v.x, v.y);
    }
}

__device__ __forceinline__ void sts_chunk(uint32_t* st, int aslot0, int bslot0,
                                          const uint32_t (&ar)[8], const uint32_t (&br)[8]) {
#pragma unroll
    for (int i = 0; i < 8; ++i) {
        st[aslot0 + 256 * i]        = ar[i];
        st[2048 + bslot0 + 256 * i] = br[i];
    }
}

// ---------------- decoder producer (R14): direct LDG -> pack -> STS, K=64 chunk -------
__device__ __forceinline__ void produce_chunk_d(uint32_t* st, int aslot0, int bslot0,
                                                const float* Ap, const float* Bp) {
#pragma unroll
    for (int sub = 0; sub < 2; ++sub) {
        uint32_t* ss = st + sub * SUBW_D;
        const float* As = Ap + sub * 32;
        const float* Bs = Bp + sub * 32;
#pragma unroll
        for (int i = 0; i < 8; ++i) {
            float2 v = *(const float2*)(As + i * 16 * FNUM);
            ss[aslot0 + 256 * i] = pack16(v.x, v.y);
        }
#pragma unroll
        for (int i = 0; i < 8; ++i) {
            float2 v = *(const float2*)(Bs + i * 16 * FNUM);
            ss[2048 + bslot0 + 256 * i] = pack16(v.x, v.y);
        }
    }
}

// ---------------- encoder (R15-proven: 128x128, 256 thr, occ 2, 1-term, prefetch) ----
__global__ __launch_bounds__(256, 2) void encoder_mma(const float* __restrict__ resid,
                                                      const float* __restrict__ enc_w,
                                                      const float* __restrict__ enc_b,
                                                      float* __restrict__ out) {
    extern __shared__ uint32_t smraw[];
    __shared__ float sbias[128];
    __shared__ float s_sp[8];
    __shared__ int   s_cnt[8];

    const int tid = threadIdx.x;
    const int l   = blockIdx.z;
    const int m0  = blockIdx.y * 128;
    const int n0  = blockIdx.x * 128;
    const uint32_t smb = smem_u32(smraw);

    if (tid < 128) sbias[tid] = enc_b[(long long)l * FNUM + n0 + tid];

    int aslot0, bslot0, gpc;
    prod_bases(tid, aslot0, bslot0, gpc);
    const int rbase = tid >> 4;
    const float* Ap = resid + ((long long)l * BNUM + m0 + rbase) * DNUM + gpc;
    const float* Bp = enc_w + ((long long)l * FNUM + n0 + rbase) * DNUM + gpc;

    float acc[4][4][4];
#pragma unroll
    for (int m = 0; m < 4; ++m)
#pragma unroll
        for (int n = 0; n < 4; ++n)
#pragma unroll
            for (int q = 0; q < 4; ++q) acc[m][n][q] = 0.0f;

    const int lane = tid & 31, wid = tid >> 5;
    const int wm = wid >> 2, wn = wid & 3;

    uint32_t ar[8], br[8];
    load_pack<DNUM>(Ap, Bp, ar, br);
    sts_chunk(smraw, aslot0, bslot0, ar, br);

    const int NC = DNUM / KC_E;   // 32
    for (int c = 0; c < NC; ++c) {
        __syncthreads();
        if (c + 1 < NC) {
            Ap += KC_E;
            Bp += KC_E;
            load_pack<DNUM>(Ap, Bp, ar, br);   // LDG hidden behind consume
        }
        consume_chunk1(smb + (c & 1) * (STW_E * 4), lane, wm, wn, acc);
        if (c + 1 < NC)
            sts_chunk(smraw + ((c + 1) & 1) * STW_E, aslot0, bslot0, ar, br);
    }

    const int g = lane >> 2, tt = lane & 3;

    float sp = 0.0f;
    int   cnt = 0;
#pragma unroll
    for (int m = 0; m < 4; ++m) {
        const int r0 = m0 + wm * 64 + m * 16 + g;
#pragma unroll
        for (int n = 0; n < 4; ++n) {
            const int cl  = wn * 32 + n * 8 + tt * 2;
            const float b0 = sbias[cl], b1 = sbias[cl + 1];
            float x0 = fmaxf(acc[m][n][0] + b0, 0.0f);
            float x1 = fmaxf(acc[m][n][1] + b1, 0.0f);
            float x2 = fmaxf(acc[m][n][2] + b0, 0.0f);
            float x3 = fmaxf(acc[m][n][3] + b1, 0.0f);
            sp  += (x0 + x1) + (x2 + x3);
            cnt += (x0 > 0.0f) + (x1 > 0.0f) + (x2 > 0.0f) + (x3 > 0.0f);
            float* p0 = out + FEATS_OFF + ((long long)l * BNUM + r0) * FNUM + n0 + cl;
            float* p1 = out + FEATS_OFF + ((long long)l * BNUM + r0 + 8) * FNUM + n0 + cl;
            *(float2*)p0 = make_float2(x0, x1);
            *(float2*)p1 = make_float2(x2, x3);
        }
    }
#pragma unroll
    for (int o = 16; o > 0; o >>= 1) {
        sp  += __shfl_down_sync(0xffffffffu, sp, o);
        cnt += __shfl_down_sync(0xffffffffu, cnt, o);
    }
    if (lane == 0) { s_sp[wid] = sp; s_cnt[wid] = cnt; }
    __syncthreads();
    if (tid == 0) {
        float tsp = 0.0f; int tc = 0;
        for (int w = 0; w < 8; ++w) { tsp += s_sp[w]; tc += s_cnt[w]; }
        atomicAdd(&g_sp_sum, (double)tsp);
        atomicAdd(&g_cnt[l], (unsigned long long)tc);
    }
}

// ---------------- decoder (R14-proven: 128x128, occ 2, KC=64, 1-term) -----------------
__global__ __launch_bounds__(256, 2) void decoder_mma(const float* __restrict__ feats,
                                                      const float* __restrict__ dec_w,
                                                      const float* __restrict__ tgt,
                                                      float* __restrict__ out) {
    extern __shared__ uint32_t smraw[];
    __shared__ float s_sq[8];

    const int tid = threadIdx.x;
    const int bid = blockIdx.x;
    const int t   = 7 - (bid >> 6);      // t descending: 3-segment CTAs first
    const int rem = bid & 63;
    const int m0  = (rem >> 3) * 128;
    const int n0  = (rem & 7) * 128;
    const uint32_t smb = smem_u32(smraw);

    int aslot0, bslot0, gpc;
    prod_bases(tid, aslot0, bslot0, gpc);
    const int rbase = tid >> 4;

    const int s_lo = (t >= 2) ? (t - 2) : 0;
    const int nseg = t - s_lo + 1;
    const int NC   = nseg * (FNUM / KC_D);   // nseg * 128

    float acc[4][4][4];
#pragma unroll
    for (int m = 0; m < 4; ++m)
#pragma unroll
        for (int n = 0; n < 4; ++n)
#pragma unroll
            for (int q = 0; q < 4; ++q) acc[m][n][q] = 0.0f;

    const int lane = tid & 31, wid = tid >> 5;
    const int wm = wid >> 2, wn = wid & 3;

    const float* Ap = nullptr;
    const float* Bp = nullptr;

    for (int c = 0; c < NC; ++c) {
        if ((c & 127) == 0) {   // segment boundary
            const int s  = s_lo + (c >> 7);
            const int pb = ((s <= 5) ? (3 * s) : (2 * s + 6)) + (t - s);
            Ap = feats + ((long long)s * BNUM + m0 + rbase) * FNUM + gpc;
            Bp = dec_w + ((long long)pb * DNUM + n0 + rbase) * FNUM + gpc;
        }
        produce_chunk_d(smraw + (c & 1) * STW_D, aslot0, bslot0, Ap, Bp);
        Ap += KC_D;
        Bp += KC_D;
        __syncthreads();
        const uint32_t base = smb + (c & 1) * (STW_D * 4);
        consume_chunk1(base, lane, wm, wn, acc);
        consume_chunk1(base + SUBW_D * 4, lane, wm, wn, acc);
    }

    const int g = lane >> 2, tt = lane & 3;

    float sq = 0.0f;
#pragma unroll
    for (int m = 0; m < 4; ++m) {
        const int r0 = m0 + wm * 64 + m * 16 + g;
#pragma unroll
        for (int n = 0; n < 4; ++n) {
            const int col = n0 + wn * 32 + n * 8 + tt * 2;
            const long long row0 = (long long)t * BNUM + r0;
            const long long row1 = row0 + 8;
            float2 t0 = *(const float2*)(tgt + row0 * DNUM + col);
            float2 t1 = *(const float2*)(tgt + row1 * DNUM + col);
            const float v0 = acc[m][n][0], v1 = acc[m][n][1];
            const float v2 = acc[m][n][2], v3 = acc[m][n][3];
            float d0 = v0 - t0.x, d1 = v1 - t0.y, d2 = v2 - t1.x, d3 = v3 - t1.y;
            sq = fmaf(d0, d0, sq); sq = fmaf(d1, d1, sq);
            sq = fmaf(d2, d2, sq); sq = fmaf(d3, d3, sq);
            *(float2*)(out + row0 * DNUM + col) = make_float2(v0, v1);
            *(float2*)(out + row1 * DNUM + col) = make_float2(v2, v3);
        }
    }
#pragma unroll
    for (int o = 16; o > 0; o >>= 1) sq += __shfl_down_sync(0xffffffffu, sq, o);
    if (lane == 0) s_sq[wid] = sq;
    __syncthreads();
    if (tid == 0) {
        float tsq = 0.0f;
        for (int w = 0; w < 8; ++w) tsq += s_sq[w];
        atomicAdd(&g_sq_sum, (double)tsq);

        // fused finalize: last CTA writes the scalar outputs
        __threadfence();
        const int old = atomicAdd(&g_done, 1);
        if (old == DEC_BLOCKS - 1) {
            g_done = 0;  // reset for next graph replay (deterministic)
            double rl = g_sq_sum / ((double)LNUM * (double)BNUM * (double)DNUM);
            double sl = 1e-4 * (g_sp_sum / ((double)LNUM * (double)BNUM * (double)FNUM));
            out[LOSS_OFF + 0] = (float)(rl + sl);
            out[LOSS_OFF + 1] = (float)rl;
            out[LOSS_OFF + 2] = (float)sl;
            for (int i = 0; i < LNUM; ++i)
                out[LOSS_OFF + 3 + i] = (float)((double)g_cnt[i] / (double)BNUM);
        }
    }
}

// ---------------- entry point ----------------
#define SMEM_ENC (2 * STW_E * 4)   // 32 KB
#define SMEM_DEC (2 * STW_D * 4)   // 64 KB

extern "C" void kernel_launch(void* const* d_in, const int* in_sizes, int n_in,
                              void* d_out, int out_size) {
    (void)in_sizes; (void)n_in; (void)out_size;
    const float* resid   = (const float*)d_in[0];
    const float* targets = (const float*)d_in[1];
    const float* enc_w   = (const float*)d_in[2];
    const float* enc_b   = (const float*)d_in[3];
    const float* dec_w   = (const float*)d_in[4];
    float* out = (float*)d_out;

    static bool attr_done = false;
    if (!attr_done) {
        cudaFuncSetAttribute(encoder_mma, cudaFuncAttributeMaxDynamicSharedMemorySize, SMEM_ENC);
        cudaFuncSetAttribute(decoder_mma, cudaFuncAttributeMaxDynamicSharedMemorySize, SMEM_DEC);
        attr_done = true;
    }

    init_acc_kernel<<<1, 1>>>();

    dim3 genc(FNUM / 128, BNUM / 128, LNUM);  // (64, 8, 8)
    encoder_mma<<<genc, 256, SMEM_ENC>>>(resid, enc_w, enc_b, out);

    spacer_kernel<<<1, 32>>>();   // keeps decoder at ncu's profiled launch slot

    decoder_mma<<<DEC_BLOCKS, 256, SMEM_DEC>>>(out + FEATS_OFF, dec_w, targets, out);
}